// round 1
// baseline (speedup 1.0000x reference)
#include <cuda_runtime.h>
#include <cstdint>

#define B 64
#define C 256
#define HW 4096
#define CS 64
#define NC 8
#define BC (B * C)   // 16384

// Scratch (device globals: no allocation allowed)
__device__ float g_sum[BC];
__device__ float g_min[BC];
__device__ float g_max[BC];
__device__ float g_scale[BC];
__device__ float g_smin[B];
__device__ float g_smax[B];
__device__ float g_ss[B];
__device__ float g_zz[B];
__device__ float g_c2[B];
__device__ float g_inv[B];

// ---------------------------------------------------------------------------
// Kernel 1: per-(b,c) sum / min / max over the 4096 spatial elements.
// 16384 blocks x 128 threads, 8 float4 per thread (batched LDG.128 -> high MLP).
// ---------------------------------------------------------------------------
__global__ __launch_bounds__(128) void reduce_kernel(const float* __restrict__ x) {
    const int bc = blockIdx.x;
    const float4* p = reinterpret_cast<const float4*>(x) + (size_t)bc * 1024;
    const int t = threadIdx.x;

    float s = 0.0f, mn = 3.4028235e38f, mx = -3.4028235e38f;
#pragma unroll
    for (int k = 0; k < 8; ++k) {
        float4 v = p[t + (k << 7)];
        s += (v.x + v.y) + (v.z + v.w);
        mn = fminf(mn, fminf(fminf(v.x, v.y), fminf(v.z, v.w)));
        mx = fmaxf(mx, fmaxf(fmaxf(v.x, v.y), fmaxf(v.z, v.w)));
    }
#pragma unroll
    for (int o = 16; o; o >>= 1) {
        s += __shfl_xor_sync(0xFFFFFFFFu, s, o);
        mn = fminf(mn, __shfl_xor_sync(0xFFFFFFFFu, mn, o));
        mx = fmaxf(mx, __shfl_xor_sync(0xFFFFFFFFu, mx, o));
    }
    __shared__ float rs[4], rn[4], rx[4];
    const int w = t >> 5;
    if ((t & 31) == 0) { rs[w] = s; rn[w] = mn; rx[w] = mx; }
    __syncthreads();
    if (t == 0) {
        g_sum[bc] = (rs[0] + rs[1]) + (rs[2] + rs[3]);
        g_min[bc] = fminf(fminf(rn[0], rn[1]), fminf(rn[2], rn[3]));
        g_max[bc] = fmaxf(fmaxf(rx[0], rx[1]), fmaxf(rx[2], rx[3]));
    }
}

// ---------------------------------------------------------------------------
// Kernel 2: per-sample SE MLP + scale + per-sample min/max of (scale * x).
// 64 blocks (one per sample b) x 256 threads.
// ---------------------------------------------------------------------------
__global__ __launch_bounds__(256) void se_kernel(const float* __restrict__ w1,
                                                 const float* __restrict__ b1,
                                                 const float* __restrict__ w2,
                                                 const float* __restrict__ b2) {
    const int b = blockIdx.x;
    const int t = threadIdx.x;
    const int w = t >> 5, lane = t & 31;

    __shared__ __align__(16) float sp[C];    // pooled row
    __shared__ __align__(16) float sh_[CS];  // hidden row
    __shared__ float rmn[8], rmx[8];

    sp[t] = g_sum[b * C + t] * (1.0f / 4096.0f);
    __syncthreads();

    // Hidden layer: warp w computes s = w*8 .. w*8+7 (coalesced w1 rows,
    // conflict-free LDS.128 on sp, shfl reduction).
#pragma unroll
    for (int si = 0; si < 8; ++si) {
        const int s = w * 8 + si;
        const float4* wrow = reinterpret_cast<const float4*>(w1 + s * C);
        const float4* pr = reinterpret_cast<const float4*>(sp);
        float acc = 0.0f;
#pragma unroll
        for (int j = 0; j < 2; ++j) {
            float4 wv = wrow[lane + j * 32];
            float4 pv = pr[lane + j * 32];
            acc += wv.x * pv.x + wv.y * pv.y + wv.z * pv.z + wv.w * pv.w;
        }
#pragma unroll
        for (int o = 16; o; o >>= 1) acc += __shfl_xor_sync(0xFFFFFFFFu, acc, o);
        if (lane == 0) sh_[s] = fmaxf(acc + b1[s], 0.0f);
    }
    __syncthreads();

    // Output layer: thread t = channel c. w2 row is contiguous per c (L1/L2 hit
    // after first block); then scale + per-sample min/max reduction.
    const int c = t;
    float v = b2[c];
    const float4* w2r = reinterpret_cast<const float4*>(w2 + c * CS);
    const float4* hr = reinterpret_cast<const float4*>(sh_);
#pragma unroll
    for (int j = 0; j < 16; ++j) {
        float4 wv = w2r[j];
        float4 hv = hr[j];
        v += wv.x * hv.x + wv.y * hv.y + wv.z * hv.z + wv.w * hv.w;
    }
    const float sc = __saturatef(v / 6.0f + 0.5f);
    const int idx = b * C + c;
    g_scale[idx] = sc;
    float pmn = sc * g_min[idx];   // scale >= 0, so min(scale*x) = scale*min(x)
    float pmx = sc * g_max[idx];
#pragma unroll
    for (int o = 16; o; o >>= 1) {
        pmn = fminf(pmn, __shfl_xor_sync(0xFFFFFFFFu, pmn, o));
        pmx = fmaxf(pmx, __shfl_xor_sync(0xFFFFFFFFu, pmx, o));
    }
    if (lane == 0) { rmn[w] = pmn; rmx[w] = pmx; }
    __syncthreads();
    if (t == 0) {
        float a = rmn[0], m = rmx[0];
#pragma unroll
        for (int i = 1; i < 8; ++i) { a = fminf(a, rmn[i]); m = fmaxf(m, rmx[i]); }
        g_smin[b] = a;
        g_smax[b] = m;
    }
}

// ---------------------------------------------------------------------------
// Kernel 3: cluster EMA + quant params. 1 block x 64 threads.
// ---------------------------------------------------------------------------
__global__ __launch_bounds__(64) void cluster_kernel(const float* __restrict__ ar,
                                                     const int* __restrict__ cl) {
    __shared__ float cs[NC], cz[NC];
    __shared__ int scl[B];
    const int t = threadIdx.x;
    scl[t] = cl[t];
    __syncthreads();
    if (t < NC) {
        float cmn = 3.4028235e38f, cmx = -3.4028235e38f;
        for (int b = 0; b < B; ++b)
            if (scl[b] == t) {
                cmn = fminf(cmn, g_smin[b]);
                cmx = fmaxf(cmx, g_smax[b]);
            }
        const float nmn = ar[2 * t] * 0.995f + cmn * (1.0f - 0.995f);
        const float nmx = ar[2 * t + 1] * 0.995f + cmx * (1.0f - 0.995f);
        const float s = (nmx - nmn) / 255.0f;
        const float z = -rintf(nmn / s);   // NaN only for empty clusters (unused)
        cs[t] = s;
        cz[t] = z;
    }
    __syncthreads();
    const int k = scl[t];
    const float s = cs[k], z = cz[k];
    g_ss[t] = s;
    g_zz[t] = z;
    g_c2[t] = -z * s;       // (q - z)*s = fma(q, s, -z*s)
    g_inv[t] = 1.0f / s;    // hoist the division out of the elementwise pass
}

// ---------------------------------------------------------------------------
// Kernel 4: fused scale + fake-quant elementwise pass.
// y = clamp(x*m1 + z, 0, 255); q = RNE(y) via magic add; out = fma(q, s, -z*s)
// 16384 blocks x 256 threads, 4 float4 per thread. Pure streaming.
// ---------------------------------------------------------------------------
__device__ __forceinline__ float quant_one(float xv, float m1, float zz,
                                           float ss, float c2) {
    float y = __fmaf_rn(xv, m1, zz);
    y = fminf(fmaxf(y, 0.0f), 255.0f);
    // round-to-nearest-even, safe for |y| < 2^22 (y in [0,255])
    float q = __fadd_rn(__fadd_rn(y, 12582912.0f), -12582912.0f);
    return __fmaf_rn(q, ss, c2);
}

__global__ __launch_bounds__(256) void quant_kernel(const float* __restrict__ x,
                                                    float* __restrict__ out) {
    const int bc = blockIdx.x;
    const int b = bc >> 8;
    const float m1 = g_scale[bc] * g_inv[b];   // scale / s  (per channel)
    const float zz = g_zz[b];
    const float ss = g_ss[b];
    const float c2 = g_c2[b];
    const float4* px = reinterpret_cast<const float4*>(x) + (size_t)bc * 1024;
    float4* po = reinterpret_cast<float4*>(out) + (size_t)bc * 1024;
    const int t = threadIdx.x;
#pragma unroll
    for (int k = 0; k < 4; ++k) {
        float4 v = px[t + (k << 8)];
        float4 o;
        o.x = quant_one(v.x, m1, zz, ss, c2);
        o.y = quant_one(v.y, m1, zz, ss, c2);
        o.z = quant_one(v.z, m1, zz, ss, c2);
        o.w = quant_one(v.w, m1, zz, ss, c2);
        po[t + (k << 8)] = o;
    }
}

extern "C" void kernel_launch(void* const* d_in, const int* in_sizes, int n_in,
                              void* d_out, int out_size) {
    (void)in_sizes; (void)n_in; (void)out_size;
    const float* x  = (const float*)d_in[0];
    const float* w1 = (const float*)d_in[1];
    const float* b1 = (const float*)d_in[2];
    const float* w2 = (const float*)d_in[3];
    const float* b2 = (const float*)d_in[4];
    const float* ar = (const float*)d_in[5];
    const int*   cl = (const int*)d_in[6];
    float* out = (float*)d_out;

    reduce_kernel<<<BC, 128>>>(x);
    se_kernel<<<B, 256>>>(w1, b1, w2, b2);
    cluster_kernel<<<1, B>>>(ar, cl);
    quant_kernel<<<BC, 256>>>(x, out);
}

// round 2
// speedup vs baseline: 1.0021x; 1.0021x over previous
#include <cuda_runtime.h>
#include <cstdint>

#define B 64
#define C 256
#define HW 4096
#define CS 64
#define NC 8
#define BC (B * C)   // 16384

// Scratch (device globals: no allocation allowed)
__device__ float g_sum[BC];
__device__ float g_min[BC];
__device__ float g_max[BC];
__device__ float g_scale[BC];
__device__ float g_smin[B];
__device__ float g_smax[B];
__device__ float g_ss[B];
__device__ float g_zz[B];
__device__ float g_c2[B];
__device__ float g_inv[B];

// ---------------------------------------------------------------------------
// Kernel 1: per-(b,c) sum / min / max over 4096 spatial elements.
// One WARP per (b,c) row: 32 x LDG.128 per lane, pure shfl tail, no smem,
// no __syncthreads. 2048 blocks x 256 threads (8 rows per block).
// ---------------------------------------------------------------------------
__global__ __launch_bounds__(256) void reduce_kernel(const float* __restrict__ x) {
    const int w = threadIdx.x >> 5;
    const int lane = threadIdx.x & 31;
    const int bc = (blockIdx.x << 3) + w;
    const float4* p = reinterpret_cast<const float4*>(x) + (size_t)bc * 1024;

    float s = 0.0f, mn = 3.4028235e38f, mx = -3.4028235e38f;
#pragma unroll
    for (int k = 0; k < 32; ++k) {
        float4 v = __ldcs(&p[lane + (k << 5)]);
        s += (v.x + v.y) + (v.z + v.w);
        mn = fminf(mn, fminf(fminf(v.x, v.y), fminf(v.z, v.w)));
        mx = fmaxf(mx, fmaxf(fmaxf(v.x, v.y), fmaxf(v.z, v.w)));
    }
#pragma unroll
    for (int o = 16; o; o >>= 1) {
        s += __shfl_xor_sync(0xFFFFFFFFu, s, o);
        mn = fminf(mn, __shfl_xor_sync(0xFFFFFFFFu, mn, o));
        mx = fmaxf(mx, __shfl_xor_sync(0xFFFFFFFFu, mx, o));
    }
    if (lane == 0) {
        g_sum[bc] = s;
        g_min[bc] = mn;
        g_max[bc] = mx;
    }
}

// ---------------------------------------------------------------------------
// Kernel 2: per-sample SE MLP + scale + per-sample min/max of (scale * x).
// 64 blocks (one per sample b) x 256 threads.
// ---------------------------------------------------------------------------
__global__ __launch_bounds__(256) void se_kernel(const float* __restrict__ w1,
                                                 const float* __restrict__ b1,
                                                 const float* __restrict__ w2,
                                                 const float* __restrict__ b2) {
    const int b = blockIdx.x;
    const int t = threadIdx.x;
    const int w = t >> 5, lane = t & 31;

    __shared__ __align__(16) float sp[C];    // pooled row
    __shared__ __align__(16) float sh_[CS];  // hidden row
    __shared__ float rmn[8], rmx[8];

    sp[t] = g_sum[b * C + t] * (1.0f / 4096.0f);
    __syncthreads();

    // Hidden layer: warp w computes s = w*8 .. w*8+7 (coalesced w1 rows,
    // conflict-free LDS.128 on sp, shfl reduction).
#pragma unroll
    for (int si = 0; si < 8; ++si) {
        const int s = w * 8 + si;
        const float4* wrow = reinterpret_cast<const float4*>(w1 + s * C);
        const float4* pr = reinterpret_cast<const float4*>(sp);
        float acc = 0.0f;
#pragma unroll
        for (int j = 0; j < 2; ++j) {
            float4 wv = wrow[lane + j * 32];
            float4 pv = pr[lane + j * 32];
            acc += wv.x * pv.x + wv.y * pv.y + wv.z * pv.z + wv.w * pv.w;
        }
#pragma unroll
        for (int o = 16; o; o >>= 1) acc += __shfl_xor_sync(0xFFFFFFFFu, acc, o);
        if (lane == 0) sh_[s] = fmaxf(acc + b1[s], 0.0f);
    }
    __syncthreads();

    // Output layer: thread t = channel c.
    const int c = t;
    float v = b2[c];
    const float4* w2r = reinterpret_cast<const float4*>(w2 + c * CS);
    const float4* hr = reinterpret_cast<const float4*>(sh_);
#pragma unroll
    for (int j = 0; j < 16; ++j) {
        float4 wv = w2r[j];
        float4 hv = hr[j];
        v += wv.x * hv.x + wv.y * hv.y + wv.z * hv.z + wv.w * hv.w;
    }
    const float sc = __saturatef(v / 6.0f + 0.5f);
    const int idx = b * C + c;
    g_scale[idx] = sc;
    float pmn = sc * g_min[idx];   // scale >= 0, so min(scale*x) = scale*min(x)
    float pmx = sc * g_max[idx];
#pragma unroll
    for (int o = 16; o; o >>= 1) {
        pmn = fminf(pmn, __shfl_xor_sync(0xFFFFFFFFu, pmn, o));
        pmx = fmaxf(pmx, __shfl_xor_sync(0xFFFFFFFFu, pmx, o));
    }
    if (lane == 0) { rmn[w] = pmn; rmx[w] = pmx; }
    __syncthreads();
    if (t == 0) {
        float a = rmn[0], m = rmx[0];
#pragma unroll
        for (int i = 1; i < 8; ++i) { a = fminf(a, rmn[i]); m = fmaxf(m, rmx[i]); }
        g_smin[b] = a;
        g_smax[b] = m;
    }
}

// ---------------------------------------------------------------------------
// Kernel 3: cluster EMA + quant params. 1 block x 64 threads.
// ---------------------------------------------------------------------------
__global__ __launch_bounds__(64) void cluster_kernel(const float* __restrict__ ar,
                                                     const int* __restrict__ cl) {
    __shared__ float cs[NC], cz[NC];
    __shared__ int scl[B];
    const int t = threadIdx.x;
    scl[t] = cl[t];
    __syncthreads();
    if (t < NC) {
        float cmn = 3.4028235e38f, cmx = -3.4028235e38f;
        for (int b = 0; b < B; ++b)
            if (scl[b] == t) {
                cmn = fminf(cmn, g_smin[b]);
                cmx = fmaxf(cmx, g_smax[b]);
            }
        const float nmn = ar[2 * t] * 0.995f + cmn * (1.0f - 0.995f);
        const float nmx = ar[2 * t + 1] * 0.995f + cmx * (1.0f - 0.995f);
        const float s = (nmx - nmn) / 255.0f;
        const float z = -rintf(nmn / s);   // NaN only for empty clusters (unused)
        cs[t] = s;
        cz[t] = z;
    }
    __syncthreads();
    const int k = scl[t];
    const float s = cs[k], z = cz[k];
    g_ss[t] = s;
    g_zz[t] = z;
    g_c2[t] = -z * s;       // (q - z)*s = fma(q, s, -z*s)
    g_inv[t] = 1.0f / s;    // hoist the division out of the elementwise pass
}

// ---------------------------------------------------------------------------
// Kernel 4: fused scale + fake-quant elementwise pass.
// y = clamp(x*m1 + z, 0, 255); q = RNE(y) via magic add; out = fma(q, s, -z*s)
// Streaming: __ldcs / __stcs (zero reuse, don't thrash L2).
// ---------------------------------------------------------------------------
__device__ __forceinline__ float quant_one(float xv, float m1, float zz,
                                           float ss, float c2) {
    float y = __fmaf_rn(xv, m1, zz);
    y = fminf(fmaxf(y, 0.0f), 255.0f);
    // round-to-nearest-even, safe for y in [0,255]
    float q = __fadd_rn(__fadd_rn(y, 12582912.0f), -12582912.0f);
    return __fmaf_rn(q, ss, c2);
}

__global__ __launch_bounds__(256) void quant_kernel(const float* __restrict__ x,
                                                    float* __restrict__ out) {
    const int bc = blockIdx.x;
    const int b = bc >> 8;
    const float m1 = g_scale[bc] * g_inv[b];   // scale / s  (per channel)
    const float zz = g_zz[b];
    const float ss = g_ss[b];
    const float c2 = g_c2[b];
    const float4* px = reinterpret_cast<const float4*>(x) + (size_t)bc * 1024;
    float4* po = reinterpret_cast<float4*>(out) + (size_t)bc * 1024;
    const int t = threadIdx.x;
#pragma unroll
    for (int k = 0; k < 4; ++k) {
        float4 v = __ldcs(&px[t + (k << 8)]);
        float4 o;
        o.x = quant_one(v.x, m1, zz, ss, c2);
        o.y = quant_one(v.y, m1, zz, ss, c2);
        o.z = quant_one(v.z, m1, zz, ss, c2);
        o.w = quant_one(v.w, m1, zz, ss, c2);
        __stcs(&po[t + (k << 8)], o);
    }
}

extern "C" void kernel_launch(void* const* d_in, const int* in_sizes, int n_in,
                              void* d_out, int out_size) {
    (void)in_sizes; (void)n_in; (void)out_size;
    const float* x  = (const float*)d_in[0];
    const float* w1 = (const float*)d_in[1];
    const float* b1 = (const float*)d_in[2];
    const float* w2 = (const float*)d_in[3];
    const float* b2 = (const float*)d_in[4];
    const float* ar = (const float*)d_in[5];
    const int*   cl = (const int*)d_in[6];
    float* out = (float*)d_out;

    reduce_kernel<<<BC / 8, 256>>>(x);
    se_kernel<<<B, 256>>>(w1, b1, w2, b2);
    cluster_kernel<<<1, B>>>(ar, cl);
    quant_kernel<<<BC, 256>>>(x, out);
}

// round 3
// speedup vs baseline: 1.0355x; 1.0333x over previous
#include <cuda_runtime.h>
#include <cstdint>

#define B 64
#define C 256
#define HW 4096
#define CS 64
#define NC 8
#define BC (B * C)   // 16384

// Scratch (device globals: no allocation allowed)
__device__ float g_sum[BC];
__device__ float g_min[BC];
__device__ float g_max[BC];
__device__ float g_scale[BC];
__device__ float g_smin[B];
__device__ float g_smax[B];
__device__ float g_ss[B];
__device__ float g_zz[B];
__device__ float g_c2[B];
__device__ float g_inv[B];

// ---------------------------------------------------------------------------
// Kernel 1: per-(b,c) sum / min / max over 4096 spatial elements.
// One WARP per (b,c) row. DEFAULT cached loads: the tail of x stays resident
// in L2 (126 MB) and the reversed quant pass re-reads it as L2 hits.
// Unroll limited to 8 to keep the L1tex wavefront queue under control.
// ---------------------------------------------------------------------------
__global__ __launch_bounds__(256) void reduce_kernel(const float* __restrict__ x) {
    const int w = threadIdx.x >> 5;
    const int lane = threadIdx.x & 31;
    const int bc = (blockIdx.x << 3) + w;
    const float4* p = reinterpret_cast<const float4*>(x) + (size_t)bc * 1024;

    float s = 0.0f, mn = 3.4028235e38f, mx = -3.4028235e38f;
#pragma unroll 8
    for (int k = 0; k < 32; ++k) {
        float4 v = p[lane + (k << 5)];
        s += (v.x + v.y) + (v.z + v.w);
        mn = fminf(mn, fminf(fminf(v.x, v.y), fminf(v.z, v.w)));
        mx = fmaxf(mx, fmaxf(fmaxf(v.x, v.y), fmaxf(v.z, v.w)));
    }
#pragma unroll
    for (int o = 16; o; o >>= 1) {
        s += __shfl_xor_sync(0xFFFFFFFFu, s, o);
        mn = fminf(mn, __shfl_xor_sync(0xFFFFFFFFu, mn, o));
        mx = fmaxf(mx, __shfl_xor_sync(0xFFFFFFFFu, mx, o));
    }
    if (lane == 0) {
        g_sum[bc] = s;
        g_min[bc] = mn;
        g_max[bc] = mx;
    }
}

// ---------------------------------------------------------------------------
// Kernel 2: per-sample SE MLP + scale + per-sample min/max of (scale * x).
// 64 blocks (one per sample b) x 256 threads.
// ---------------------------------------------------------------------------
__global__ __launch_bounds__(256) void se_kernel(const float* __restrict__ w1,
                                                 const float* __restrict__ b1,
                                                 const float* __restrict__ w2,
                                                 const float* __restrict__ b2) {
    const int b = blockIdx.x;
    const int t = threadIdx.x;
    const int w = t >> 5, lane = t & 31;

    __shared__ __align__(16) float sp[C];    // pooled row
    __shared__ __align__(16) float sh_[CS];  // hidden row
    __shared__ float rmn[8], rmx[8];

    sp[t] = g_sum[b * C + t] * (1.0f / 4096.0f);
    __syncthreads();

    // Hidden layer: warp w computes s = w*8 .. w*8+7.
#pragma unroll
    for (int si = 0; si < 8; ++si) {
        const int s = w * 8 + si;
        const float4* wrow = reinterpret_cast<const float4*>(w1 + s * C);
        const float4* pr = reinterpret_cast<const float4*>(sp);
        float acc = 0.0f;
#pragma unroll
        for (int j = 0; j < 2; ++j) {
            float4 wv = wrow[lane + j * 32];
            float4 pv = pr[lane + j * 32];
            acc += wv.x * pv.x + wv.y * pv.y + wv.z * pv.z + wv.w * pv.w;
        }
#pragma unroll
        for (int o = 16; o; o >>= 1) acc += __shfl_xor_sync(0xFFFFFFFFu, acc, o);
        if (lane == 0) sh_[s] = fmaxf(acc + b1[s], 0.0f);
    }
    __syncthreads();

    // Output layer: thread t = channel c.
    const int c = t;
    float v = b2[c];
    const float4* w2r = reinterpret_cast<const float4*>(w2 + c * CS);
    const float4* hr = reinterpret_cast<const float4*>(sh_);
#pragma unroll
    for (int j = 0; j < 16; ++j) {
        float4 wv = w2r[j];
        float4 hv = hr[j];
        v += wv.x * hv.x + wv.y * hv.y + wv.z * hv.z + wv.w * hv.w;
    }
    const float sc = __saturatef(v / 6.0f + 0.5f);
    const int idx = b * C + c;
    g_scale[idx] = sc;
    float pmn = sc * g_min[idx];   // scale >= 0
    float pmx = sc * g_max[idx];
#pragma unroll
    for (int o = 16; o; o >>= 1) {
        pmn = fminf(pmn, __shfl_xor_sync(0xFFFFFFFFu, pmn, o));
        pmx = fmaxf(pmx, __shfl_xor_sync(0xFFFFFFFFu, pmx, o));
    }
    if (lane == 0) { rmn[w] = pmn; rmx[w] = pmx; }
    __syncthreads();
    if (t == 0) {
        float a = rmn[0], m = rmx[0];
#pragma unroll
        for (int i = 1; i < 8; ++i) { a = fminf(a, rmn[i]); m = fmaxf(m, rmx[i]); }
        g_smin[b] = a;
        g_smax[b] = m;
    }
}

// ---------------------------------------------------------------------------
// Kernel 3: cluster EMA + quant params. 1 block x 64 threads.
// ---------------------------------------------------------------------------
__global__ __launch_bounds__(64) void cluster_kernel(const float* __restrict__ ar,
                                                     const int* __restrict__ cl) {
    __shared__ float cs[NC], cz[NC];
    __shared__ int scl[B];
    const int t = threadIdx.x;
    scl[t] = cl[t];
    __syncthreads();
    if (t < NC) {
        float cmn = 3.4028235e38f, cmx = -3.4028235e38f;
        for (int b = 0; b < B; ++b)
            if (scl[b] == t) {
                cmn = fminf(cmn, g_smin[b]);
                cmx = fmaxf(cmx, g_smax[b]);
            }
        const float nmn = ar[2 * t] * 0.995f + cmn * (1.0f - 0.995f);
        const float nmx = ar[2 * t + 1] * 0.995f + cmx * (1.0f - 0.995f);
        const float s = (nmx - nmn) / 255.0f;
        const float z = -rintf(nmn / s);
        cs[t] = s;
        cz[t] = z;
    }
    __syncthreads();
    const int k = scl[t];
    const float s = cs[k], z = cz[k];
    g_ss[t] = s;
    g_zz[t] = z;
    g_c2[t] = -z * s;       // (q - z)*s = fma(q, s, -z*s)
    g_inv[t] = 1.0f / s;
}

// ---------------------------------------------------------------------------
// Kernel 4: fused scale + fake-quant elementwise pass.
// REVERSED block order: first waves read the x lines reduce left in L2.
// Loads default (so they can hit L2); stores evict-first (__stcs) so the
// output stream doesn't evict the x lines we're about to hit.
// ---------------------------------------------------------------------------
__device__ __forceinline__ float quant_one(float xv, float m1, float zz,
                                           float ss, float c2) {
    float y = __fmaf_rn(xv, m1, zz);
    y = fminf(fmaxf(y, 0.0f), 255.0f);
    // round-to-nearest-even via magic add, y in [0,255]
    float q = __fadd_rn(__fadd_rn(y, 12582912.0f), -12582912.0f);
    return __fmaf_rn(q, ss, c2);
}

__global__ __launch_bounds__(256) void quant_kernel(const float* __restrict__ x,
                                                    float* __restrict__ out) {
    const int bc = (BC - 1) - blockIdx.x;   // reverse order for L2 reuse
    const int b = bc >> 8;
    const float m1 = g_scale[bc] * g_inv[b];   // scale / s  (per channel)
    const float zz = g_zz[b];
    const float ss = g_ss[b];
    const float c2 = g_c2[b];
    const float4* px = reinterpret_cast<const float4*>(x) + (size_t)bc * 1024;
    float4* po = reinterpret_cast<float4*>(out) + (size_t)bc * 1024;
    const int t = threadIdx.x;
#pragma unroll
    for (int k = 0; k < 4; ++k) {
        float4 v = px[t + (k << 8)];
        float4 o;
        o.x = quant_one(v.x, m1, zz, ss, c2);
        o.y = quant_one(v.y, m1, zz, ss, c2);
        o.z = quant_one(v.z, m1, zz, ss, c2);
        o.w = quant_one(v.w, m1, zz, ss, c2);
        __stcs(&po[t + (k << 8)], o);
    }
}

extern "C" void kernel_launch(void* const* d_in, const int* in_sizes, int n_in,
                              void* d_out, int out_size) {
    (void)in_sizes; (void)n_in; (void)out_size;
    const float* x  = (const float*)d_in[0];
    const float* w1 = (const float*)d_in[1];
    const float* b1 = (const float*)d_in[2];
    const float* w2 = (const float*)d_in[3];
    const float* b2 = (const float*)d_in[4];
    const float* ar = (const float*)d_in[5];
    const int*   cl = (const int*)d_in[6];
    float* out = (float*)d_out;

    reduce_kernel<<<BC / 8, 256>>>(x);
    se_kernel<<<B, 256>>>(w1, b1, w2, b2);
    cluster_kernel<<<1, B>>>(ar, cl);
    quant_kernel<<<BC, 256>>>(x, out);
}